// round 1
// baseline (speedup 1.0000x reference)
#include <cuda_runtime.h>
#include <math.h>

#define BATCH 4
#define CH    96
#define HRES  256
#define WRES  256
#define HW    65536
#define HEADS 3
#define HD    32
#define NPOS  64            // positions per 8x8 window
#define NWIN  4096          // total windows (4 batches * 32 * 32)
#define QSCALE 0.17677669529663687f   // 32^-0.5

// ---------------- scratch (device globals; no runtime allocation) ----------
__device__ float g_V  [BATCH*CH*HW];          // V in NCHW (for depthwise conv)
__device__ float g_q  [NWIN*HEADS*HD*NPOS];   // [win][head][d][n], pre-scaled
__device__ float g_k  [NWIN*HEADS*HD*NPOS];
__device__ float g_v  [NWIN*HEADS*HD*NPOS];
__device__ float g_att[BATCH*HW*CH];          // attention out, channels-last [b][h][w][c]
__device__ float g_bias[HEADS*NPOS*NPOS];     // relative-position bias table

// ---------------- kernel B: bias MLP table  [3][64][64] --------------------
__global__ void bias_kernel(const float* __restrict__ Wm1, const float* __restrict__ bm1,
                            const float* __restrict__ Wm2, const float* __restrict__ bm2)
{
    int gid = blockIdx.x * 256 + threadIdx.x;   // 0..4095 = n*64+m
    int n = gid >> 6, m = gid & 63;
    float r0 = (float)((n >> 3) - (m >> 3));
    float r1 = (float)((n & 7)  - (m & 7));
    r0 = copysignf(log1pf(fabsf(r0)), r0);
    r1 = copysignf(log1pf(fabsf(r1)), r1);
    float a0 = bm2[0], a1 = bm2[1], a2 = bm2[2];
    for (int j = 0; j < 256; j++) {
        float h = fmaf(r0, Wm1[j], fmaf(r1, Wm1[256 + j], bm1[j]));
        h = fmaxf(h, 0.f);
        a0 = fmaf(h, Wm2[j*3 + 0], a0);
        a1 = fmaf(h, Wm2[j*3 + 1], a1);
        a2 = fmaf(h, Wm2[j*3 + 2], a2);
    }
    g_bias[0*4096 + gid] = a0;
    g_bias[1*4096 + gid] = a1;
    g_bias[2*4096 + gid] = a2;
}

// ---------------- kernel A: fused QKV 1x1 conv GEMM ------------------------
// out channels o in [0,288): 0..95=Q, 96..191=K, 192..287=V (Wqk rows then Wv)
// Tile: 64 pixels x 48 output channels, 256 threads, each 4px x 3ch.
__global__ __launch_bounds__(256) void qkv_kernel(
    const float* __restrict__ x,
    const float* __restrict__ Wqk, const float* __restrict__ bqk,
    const float* __restrict__ Wv,  const float* __restrict__ bv)
{
    __shared__ float x_s[96][64];
    __shared__ float w_s[96][49];   // [k][c], padded (49 odd -> conflict-free)

    int t   = blockIdx.x;           // pixel tile (0..4095)
    int b   = t >> 10;
    int hw0 = (t & 1023) << 6;      // 64 consecutive w in one row
    int ch0 = blockIdx.y * 48;
    int tid = threadIdx.x;

    for (int idx = tid; idx < 96*64; idx += 256) {
        int k = idx >> 6, p = idx & 63;
        x_s[k][p] = x[(b*96 + k)*HW + hw0 + p];
    }
    for (int idx = tid; idx < 96*48; idx += 256) {
        int k = idx % 96, c = idx / 96;     // lanes vary k -> coalesced global
        int o = ch0 + c;
        w_s[k][c] = (o < 192) ? Wqk[o*96 + k] : Wv[(o - 192)*96 + k];
    }
    __syncthreads();

    int pxg = tid & 15, chg = tid >> 4;
    int cb  = chg * 3;
    float acc[3][4];
    #pragma unroll
    for (int i = 0; i < 3; i++)
        #pragma unroll
        for (int j = 0; j < 4; j++) acc[i][j] = 0.f;

    #pragma unroll 4
    for (int k = 0; k < 96; k++) {
        float4 xv = *(const float4*)&x_s[k][pxg*4];
        float w0 = w_s[k][cb], w1 = w_s[k][cb+1], w2 = w_s[k][cb+2];
        acc[0][0] = fmaf(w0, xv.x, acc[0][0]);
        acc[0][1] = fmaf(w0, xv.y, acc[0][1]);
        acc[0][2] = fmaf(w0, xv.z, acc[0][2]);
        acc[0][3] = fmaf(w0, xv.w, acc[0][3]);
        acc[1][0] = fmaf(w1, xv.x, acc[1][0]);
        acc[1][1] = fmaf(w1, xv.y, acc[1][1]);
        acc[1][2] = fmaf(w1, xv.z, acc[1][2]);
        acc[1][3] = fmaf(w1, xv.w, acc[1][3]);
        acc[2][0] = fmaf(w2, xv.x, acc[2][0]);
        acc[2][1] = fmaf(w2, xv.y, acc[2][1]);
        acc[2][2] = fmaf(w2, xv.z, acc[2][2]);
        acc[2][3] = fmaf(w2, xv.w, acc[2][3]);
    }

    // epilogue: 4 consecutive pixels stay inside one window (offsets align mod 4)
    int p0 = pxg * 4;
    int hw = hw0 + p0;
    int h  = hw >> 8, w = hw & 255;
    int hp = (h + 252) & 255;               // rolled coords (roll by -4)
    int wp = (w + 252) & 255;
    int wh = hp >> 3, r = hp & 7, ww = wp >> 3, cc = wp & 7;
    int win = b*1024 + wh*32 + ww;
    int n   = r*8 + cc;                     // n..n+3 contiguous
    int grp = ch0 / 96;                     // 0=Q 1=K 2=V (constant per block)

    #pragma unroll
    for (int ci = 0; ci < 3; ci++) {
        int o = ch0 + cb + ci;
        float bia = (o < 192) ? bqk[o] : bv[o - 192];
        float4 v4 = make_float4(acc[ci][0] + bia, acc[ci][1] + bia,
                                acc[ci][2] + bia, acc[ci][3] + bia);
        int cg = o % 96;
        int head = cg >> 5, d = cg & 31;
        int qi = ((win*3 + head)*32 + d)*64 + n;
        if (grp == 0) {
            float4 s4 = make_float4(v4.x*QSCALE, v4.y*QSCALE, v4.z*QSCALE, v4.w*QSCALE);
            *(float4*)&g_q[qi] = s4;
        } else if (grp == 1) {
            *(float4*)&g_k[qi] = v4;
        } else {
            *(float4*)&g_v[qi] = v4;
            *(float4*)&g_V[(b*96 + cg)*HW + hw] = v4;
        }
    }
}

// ---------------- kernel C: windowed attention ------------------------------
// one block = (window, head), 64 threads = 64 query rows
__device__ __forceinline__ int swin_label(int wh, int ww, int idx) {
    int rh = (wh == 31) ? (1 + (((idx >> 3) >= 4) ? 1 : 0)) : 0;
    int rw = (ww == 31) ? (1 + (((idx & 7)  >= 4) ? 1 : 0)) : 0;
    return rh*3 + rw;
}

__global__ __launch_bounds__(64) void attn_kernel()
{
    __shared__ float k_s[32*64];
    __shared__ float v_s[32*64];
    __shared__ float s_s[64*65];   // padded row 65 -> conflict-free column reads

    int win  = blockIdx.x;
    int head = blockIdx.y;
    int n    = threadIdx.x;
    int base = (win*3 + head) * 2048;     // [d][n] tile, 32*64

    for (int idx = n; idx < 2048; idx += 64) {
        k_s[idx] = g_k[base + idx];
        v_s[idx] = g_v[base + idx];
    }
    float qreg[32];
    const float* qp = g_q + base;
    #pragma unroll
    for (int d = 0; d < 32; d++) qreg[d] = qp[d*64 + n];
    __syncthreads();

    int wloc = win & 1023;
    int wh = wloc >> 5, ww = wloc & 31;
    bool masked = (wh == 31) || (ww == 31);
    int labn = masked ? swin_label(wh, ww, n) : 0;

    const float* brow = g_bias + head*4096 + n*64;
    float mx = -1e30f;
    for (int m = 0; m < 64; m++) {
        float s = brow[m];
        #pragma unroll
        for (int d = 0; d < 32; d++) s = fmaf(qreg[d], k_s[d*64 + m], s);
        if (masked && swin_label(wh, ww, m) != labn) s -= 100.f;
        s_s[n*65 + m] = s;
        mx = fmaxf(mx, s);
    }
    float sum = 0.f;
    for (int m = 0; m < 64; m++) {
        float e = __expf(s_s[n*65 + m] - mx);
        sum += e;
        s_s[n*65 + m] = e;
    }
    float out[32];
    #pragma unroll
    for (int d = 0; d < 32; d++) out[d] = 0.f;
    for (int m = 0; m < 64; m++) {
        float p = s_s[n*65 + m];
        #pragma unroll
        for (int d = 0; d < 32; d++) out[d] = fmaf(p, v_s[d*64 + m], out[d]);
    }
    float inv = 1.f / sum;

    // un-window + roll back (+4), write channels-last
    int b = win >> 10;
    int r = n >> 3, c = n & 7;
    int h = ((wh << 3) + r + 4) & 255;
    int w = ((ww << 3) + c + 4) & 255;
    float* ap = g_att + ((b*256 + h)*256 + w)*96 + head*32;
    #pragma unroll
    for (int d = 0; d < 32; d += 4) {
        float4 v4 = make_float4(out[d]*inv, out[d+1]*inv, out[d+2]*inv, out[d+3]*inv);
        *(float4*)&ap[d] = v4;
    }
}

// ---------------- kernel D: depthwise 5x5 (reflect) + add attn + final 1x1 --
__global__ __launch_bounds__(256) void final_kernel(
    const float* __restrict__ Wdw, const float* __restrict__ bdw,
    const float* __restrict__ Wp,  const float* __restrict__ bp,
    float* __restrict__ outp)
{
    __shared__ float t_s[64][97];   // [pixel][channel], padded
    __shared__ float w_s[32][97];   // Wp chunk [k][o], padded

    int t   = blockIdx.x;
    int b   = t >> 10;
    int hw0 = (t & 1023) << 6;
    int h   = hw0 >> 8, w0 = hw0 & 255;
    int tid = threadIdx.x;

    // phase 1a: depthwise conv (lanes sweep pixels -> coalesced V reads)
    for (int idx = tid; idx < 96*64; idx += 256) {
        int c = idx >> 6, p = idx & 63;
        float acc = bdw[c];
        const float* vc = g_V + (b*96 + c)*HW;
        const float* wk = Wdw + c*25;
        #pragma unroll
        for (int i = 0; i < 5; i++) {
            int hh = h - 2 + i;
            hh = (hh < 0) ? -hh : ((hh > 255) ? 510 - hh : hh);
            const float* vrow = vc + hh*256;
            #pragma unroll
            for (int j = 0; j < 5; j++) {
                int wq = w0 + p - 2 + j;
                wq = (wq < 0) ? -wq : ((wq > 255) ? 510 - wq : wq);
                acc = fmaf(vrow[wq], wk[i*5 + j], acc);
            }
        }
        t_s[p][c] = acc;
    }
    __syncthreads();

    // phase 1b: add attention output (channels-last, float4 coalesced)
    const float* ab = g_att + ((b*256 + h)*256 + w0)*96;
    for (int idx = tid; idx < 64*24; idx += 256) {
        int f4 = idx % 24, p = idx / 24;
        float4 a4 = *(const float4*)&ab[p*96 + f4*4];
        int c = f4*4;
        t_s[p][c]     += a4.x;
        t_s[p][c + 1] += a4.y;
        t_s[p][c + 2] += a4.z;
        t_s[p][c + 3] += a4.w;
    }
    __syncthreads();

    // phase 2: 96x96 GEMM, K chunked by 32
    int pxg = tid & 15, chg = tid >> 4;
    int p0 = pxg*4, ob = chg*6;
    float acc[6][4];
    #pragma unroll
    for (int i = 0; i < 6; i++)
        #pragma unroll
        for (int j = 0; j < 4; j++) acc[i][j] = 0.f;

    for (int kc = 0; kc < 3; kc++) {
        if (kc) __syncthreads();
        for (int idx = tid; idx < 32*96; idx += 256) {
            int kk = idx & 31, o = idx >> 5;        // lanes vary kk -> coalesced
            w_s[kk][o] = Wp[o*96 + kc*32 + kk];
        }
        __syncthreads();
        #pragma unroll 4
        for (int kk = 0; kk < 32; kk++) {
            int k = kc*32 + kk;
            float tv0 = t_s[p0][k],   tv1 = t_s[p0+1][k];
            float tv2 = t_s[p0+2][k], tv3 = t_s[p0+3][k];
            #pragma unroll
            for (int i = 0; i < 6; i++) {
                float wv = w_s[kk][ob + i];
                acc[i][0] = fmaf(wv, tv0, acc[i][0]);
                acc[i][1] = fmaf(wv, tv1, acc[i][1]);
                acc[i][2] = fmaf(wv, tv2, acc[i][2]);
                acc[i][3] = fmaf(wv, tv3, acc[i][3]);
            }
        }
    }

    #pragma unroll
    for (int i = 0; i < 6; i++) {
        int o = ob + i;
        float bo = bp[o];
        float4 v4 = make_float4(acc[i][0] + bo, acc[i][1] + bo,
                                acc[i][2] + bo, acc[i][3] + bo);
        *(float4*)&outp[(b*96 + o)*HW + hw0 + p0] = v4;
    }
}

// ---------------- launch ----------------------------------------------------
extern "C" void kernel_launch(void* const* d_in, const int* in_sizes, int n_in,
                              void* d_out, int out_size)
{
    const float* x   = (const float*)d_in[0];
    const float* Wv  = (const float*)d_in[1];
    const float* bv  = (const float*)d_in[2];
    const float* Wqk = (const float*)d_in[3];
    const float* bqk = (const float*)d_in[4];
    const float* Wm1 = (const float*)d_in[5];
    const float* bm1 = (const float*)d_in[6];
    const float* Wm2 = (const float*)d_in[7];
    const float* bm2 = (const float*)d_in[8];
    const float* Wdw = (const float*)d_in[9];
    const float* bdw = (const float*)d_in[10];
    const float* Wp  = (const float*)d_in[11];
    const float* bp  = (const float*)d_in[12];
    float* outp = (float*)d_out;

    bias_kernel <<<16, 256>>>(Wm1, bm1, Wm2, bm2);
    qkv_kernel  <<<dim3(4096, 6), 256>>>(x, Wqk, bqk, Wv, bv);
    attn_kernel <<<dim3(4096, 3), 64>>>();
    final_kernel<<<4096, 256>>>(Wdw, bdw, Wp, bp, outp);
}

// round 2
// speedup vs baseline: 1.3906x; 1.3906x over previous
#include <cuda_runtime.h>
#include <math.h>

#define BATCH 4
#define CH    96
#define HRES  256
#define WRES  256
#define HW    65536
#define HEADS 3
#define HD    32
#define NPOS  64
#define NWIN  4096
#define QSCALE 0.17677669529663687f

// ---------------- scratch (device globals; no runtime allocation) ----------
__device__ float g_V   [BATCH*CH*HW];          // V in NCHW (input to depthwise)
__device__ float g_conv[BATCH*CH*HW];          // depthwise output, NCHW
__device__ float g_q   [NWIN*HEADS*HD*NPOS];   // [win][head][d][n], pre-scaled
__device__ float g_k   [NWIN*HEADS*HD*NPOS];
__device__ float g_v   [NWIN*HEADS*HD*NPOS];
__device__ float g_att [BATCH*HW*CH];          // attention out, channels-last
__device__ float g_bias[HEADS*NPOS*NPOS];

// ---------------- kernel B: bias MLP table  [3][64][64] --------------------
__global__ void bias_kernel(const float* __restrict__ Wm1, const float* __restrict__ bm1,
                            const float* __restrict__ Wm2, const float* __restrict__ bm2)
{
    int gid = blockIdx.x * 256 + threadIdx.x;
    int n = gid >> 6, m = gid & 63;
    float r0 = (float)((n >> 3) - (m >> 3));
    float r1 = (float)((n & 7)  - (m & 7));
    r0 = copysignf(log1pf(fabsf(r0)), r0);
    r1 = copysignf(log1pf(fabsf(r1)), r1);
    float a0 = bm2[0], a1 = bm2[1], a2 = bm2[2];
    for (int j = 0; j < 256; j++) {
        float h = fmaf(r0, Wm1[j], fmaf(r1, Wm1[256 + j], bm1[j]));
        h = fmaxf(h, 0.f);
        a0 = fmaf(h, Wm2[j*3 + 0], a0);
        a1 = fmaf(h, Wm2[j*3 + 1], a1);
        a2 = fmaf(h, Wm2[j*3 + 2], a2);
    }
    g_bias[0*4096 + gid] = a0;
    g_bias[1*4096 + gid] = a1;
    g_bias[2*4096 + gid] = a2;
}

// ---------------- kernel A: fused QKV 1x1 conv GEMM ------------------------
// 128 threads, each 4px x 6ch. Block: 64 pixels x 48 out-channels.
__global__ __launch_bounds__(128) void qkv_kernel(
    const float* __restrict__ x,
    const float* __restrict__ Wqk, const float* __restrict__ bqk,
    const float* __restrict__ Wv,  const float* __restrict__ bv)
{
    __shared__ float x_s[96][64];
    __shared__ float w_s[96][49];

    int t   = blockIdx.x;
    int b   = t >> 10;
    int hw0 = (t & 1023) << 6;
    int ch0 = blockIdx.y * 48;
    int tid = threadIdx.x;

    for (int idx = tid; idx < 96*16; idx += 128) {
        int k = idx >> 4, p4 = idx & 15;
        *(float4*)&x_s[k][p4*4] = *(const float4*)&x[(b*96 + k)*HW + hw0 + p4*4];
    }
    for (int idx = tid; idx < 96*48; idx += 128) {
        int k = idx % 96, c = idx / 96;
        int o = ch0 + c;
        w_s[k][c] = (o < 192) ? Wqk[o*96 + k] : Wv[(o - 192)*96 + k];
    }
    __syncthreads();

    int pxg = tid & 15, chg = tid >> 4;   // 16 pixel groups x 8 channel groups
    int cb  = chg * 6;
    float acc[6][4];
    #pragma unroll
    for (int i = 0; i < 6; i++)
        #pragma unroll
        for (int j = 0; j < 4; j++) acc[i][j] = 0.f;

    #pragma unroll 4
    for (int k = 0; k < 96; k++) {
        float4 xv = *(const float4*)&x_s[k][pxg*4];
        #pragma unroll
        for (int i = 0; i < 6; i++) {
            float wv = w_s[k][cb + i];
            acc[i][0] = fmaf(wv, xv.x, acc[i][0]);
            acc[i][1] = fmaf(wv, xv.y, acc[i][1]);
            acc[i][2] = fmaf(wv, xv.z, acc[i][2]);
            acc[i][3] = fmaf(wv, xv.w, acc[i][3]);
        }
    }

    int p0 = pxg * 4;
    int hw = hw0 + p0;
    int h  = hw >> 8, w = hw & 255;
    int hp = (h + 252) & 255;
    int wp = (w + 252) & 255;
    int wh = hp >> 3, r = hp & 7, ww = wp >> 3, cc = wp & 7;
    int win = b*1024 + wh*32 + ww;
    int n   = r*8 + cc;
    int grp = ch0 / 96;

    #pragma unroll
    for (int ci = 0; ci < 6; ci++) {
        int o = ch0 + cb + ci;
        float bia = (o < 192) ? bqk[o] : bv[o - 192];
        float4 v4 = make_float4(acc[ci][0] + bia, acc[ci][1] + bia,
                                acc[ci][2] + bia, acc[ci][3] + bia);
        int cg = o % 96;
        int head = cg >> 5, d = cg & 31;
        int qi = ((win*3 + head)*32 + d)*64 + n;
        if (grp == 0) {
            *(float4*)&g_q[qi] = make_float4(v4.x*QSCALE, v4.y*QSCALE,
                                             v4.z*QSCALE, v4.w*QSCALE);
        } else if (grp == 1) {
            *(float4*)&g_k[qi] = v4;
        } else {
            *(float4*)&g_v[qi] = v4;
            *(float4*)&g_V[(b*96 + cg)*HW + hw] = v4;
        }
    }
}

// ---------------- kernel DW: depthwise 5x5, reflect, smem halo -------------
__global__ __launch_bounds__(256) void dw_kernel(const float* __restrict__ Wdw,
                                                 const float* __restrict__ bdw)
{
    __shared__ float s[36][37];
    __shared__ float wk[25];

    int blk  = blockIdx.x;
    int img  = blk >> 6;                  // b*96 + c
    int tile = blk & 63;
    int c    = img % 96;
    int h0   = (tile >> 3) << 5, w0 = (tile & 7) << 5;
    int tid  = threadIdx.x;

    if (tid < 25) wk[tid] = Wdw[c*25 + tid];
    const float* vimg = g_V + (size_t)img * HW;
    for (int idx = tid; idx < 36*36; idx += 256) {
        int r  = idx / 36, cc = idx % 36;
        int hh = h0 - 2 + r;  hh = (hh < 0) ? -hh : ((hh > 255) ? 510 - hh : hh);
        int wq = w0 - 2 + cc; wq = (wq < 0) ? -wq : ((wq > 255) ? 510 - wq : wq);
        s[r][cc] = vimg[hh*256 + wq];
    }
    __syncthreads();

    float b0 = bdw[c];
    #pragma unroll
    for (int kq = 0; kq < 4; kq++) {
        int px = tid + kq*256;
        int y = px >> 5, xq = px & 31;
        float acc = b0;
        #pragma unroll
        for (int i = 0; i < 5; i++)
            #pragma unroll
            for (int j = 0; j < 5; j++)
                acc = fmaf(s[y + i][xq + j], wk[i*5 + j], acc);
        g_conv[(size_t)img*HW + (h0 + y)*256 + (w0 + xq)] = acc;
    }
}

// ---------------- kernel C: windowed attention ------------------------------
__device__ __forceinline__ int swin_label(int wh, int ww, int idx) {
    int rh = (wh == 31) ? (1 + (((idx >> 3) >= 4) ? 1 : 0)) : 0;
    int rw = (ww == 31) ? (1 + (((idx & 7)  >= 4) ? 1 : 0)) : 0;
    return rh*3 + rw;
}

__global__ __launch_bounds__(64) void attn_kernel()
{
    __shared__ float k_s[2048];
    __shared__ float v_s[2048];
    __shared__ float s_s[64*65];

    int win  = blockIdx.x;
    int head = blockIdx.y;
    int n    = threadIdx.x;
    size_t base = (size_t)(win*3 + head) * 2048;

    for (int idx = n; idx < 512; idx += 64) {
        ((float4*)k_s)[idx] = ((const float4*)(g_k + base))[idx];
        ((float4*)v_s)[idx] = ((const float4*)(g_v + base))[idx];
    }
    float qreg[32];
    const float* qp = g_q + base;
    #pragma unroll
    for (int d = 0; d < 32; d++) qreg[d] = qp[d*64 + n];
    __syncthreads();

    int wloc = win & 1023;
    int wh = wloc >> 5, ww = wloc & 31;
    bool masked = (wh == 31) || (ww == 31);
    int labn = masked ? swin_label(wh, ww, n) : 0;

    const float* brow = g_bias + head*4096 + n*64;
    float mx = -1e30f;
    for (int m = 0; m < 64; m += 8) {
        float4 b0 = *(const float4*)&brow[m];
        float4 b1 = *(const float4*)&brow[m + 4];
        float a[8] = {b0.x, b0.y, b0.z, b0.w, b1.x, b1.y, b1.z, b1.w};
        #pragma unroll
        for (int d = 0; d < 32; d++) {
            float q = qreg[d];
            float4 k0 = *(const float4*)&k_s[d*64 + m];
            float4 k1 = *(const float4*)&k_s[d*64 + m + 4];
            a[0] = fmaf(q, k0.x, a[0]);
            a[1] = fmaf(q, k0.y, a[1]);
            a[2] = fmaf(q, k0.z, a[2]);
            a[3] = fmaf(q, k0.w, a[3]);
            a[4] = fmaf(q, k1.x, a[4]);
            a[5] = fmaf(q, k1.y, a[5]);
            a[6] = fmaf(q, k1.z, a[6]);
            a[7] = fmaf(q, k1.w, a[7]);
        }
        #pragma unroll
        for (int i = 0; i < 8; i++) {
            float s = a[i];
            if (masked && swin_label(wh, ww, m + i) != labn) s -= 100.f;
            s_s[n*65 + m + i] = s;
            mx = fmaxf(mx, s);
        }
    }

    float sum = 0.f;
    #pragma unroll
    for (int m = 0; m < 64; m++) {
        float e = __expf(s_s[n*65 + m] - mx);
        sum += e;
        s_s[n*65 + m] = e;
    }

    float out[32];
    #pragma unroll
    for (int d = 0; d < 32; d++) out[d] = 0.f;
    for (int m = 0; m < 64; m += 4) {
        float p0 = s_s[n*65 + m],     p1 = s_s[n*65 + m + 1];
        float p2 = s_s[n*65 + m + 2], p3 = s_s[n*65 + m + 3];
        #pragma unroll
        for (int d = 0; d < 32; d++) {
            float4 vv = *(const float4*)&v_s[d*64 + m];
            out[d] = fmaf(p0, vv.x, fmaf(p1, vv.y,
                     fmaf(p2, vv.z, fmaf(p3, vv.w, out[d]))));
        }
    }
    float inv = 1.f / sum;

    int b = win >> 10;
    int r = n >> 3, c = n & 7;
    int h = ((wh << 3) + r + 4) & 255;
    int w = ((ww << 3) + c + 4) & 255;
    float* ap = g_att + ((size_t)(b*256 + h)*256 + w)*96 + head*32;
    #pragma unroll
    for (int d = 0; d < 32; d += 4) {
        *(float4*)&ap[d] = make_float4(out[d]*inv, out[d+1]*inv,
                                       out[d+2]*inv, out[d+3]*inv);
    }
}

// ---------------- kernel D: add (conv + attn), final 96x96 GEMM ------------
__global__ __launch_bounds__(256) void final_kernel(
    const float* __restrict__ Wp, const float* __restrict__ bp,
    float* __restrict__ outp)
{
    __shared__ float t_s[64][97];
    __shared__ float w_s[32][97];

    int t   = blockIdx.x;
    int b   = t >> 10;
    int hw0 = (t & 1023) << 6;
    int h   = hw0 >> 8, w0 = hw0 & 255;
    (void)w0;
    int tid = threadIdx.x;

    // load depthwise output (NCHW, coalesced float4), transpose into t_s
    for (int idx = tid; idx < 96*16; idx += 256) {
        int c = idx >> 4, pq = idx & 15;
        float4 v4 = *(const float4*)&g_conv[((size_t)b*96 + c)*HW + hw0 + pq*4];
        t_s[pq*4 + 0][c] = v4.x;
        t_s[pq*4 + 1][c] = v4.y;
        t_s[pq*4 + 2][c] = v4.z;
        t_s[pq*4 + 3][c] = v4.w;
    }
    __syncthreads();

    // add attention (channels-last, float4 coalesced)
    const float* ab = g_att + ((size_t)(b*256 + h)*256 + (hw0 & 255))*96;
    for (int idx = tid; idx < 64*24; idx += 256) {
        int f4 = idx % 24, p = idx / 24;
        float4 a4 = *(const float4*)&ab[p*96 + f4*4];
        int c = f4*4;
        t_s[p][c]     += a4.x;
        t_s[p][c + 1] += a4.y;
        t_s[p][c + 2] += a4.z;
        t_s[p][c + 3] += a4.w;
    }
    __syncthreads();

    int pxg = tid & 15, chg = tid >> 4;
    int p0 = pxg*4, ob = chg*6;
    float acc[6][4];
    #pragma unroll
    for (int i = 0; i < 6; i++)
        #pragma unroll
        for (int j = 0; j < 4; j++) acc[i][j] = 0.f;

    for (int kc = 0; kc < 3; kc++) {
        if (kc) __syncthreads();
        for (int idx = tid; idx < 32*96; idx += 256) {
            int kk = idx & 31, o = idx >> 5;
            w_s[kk][o] = Wp[o*96 + kc*32 + kk];
        }
        __syncthreads();
        #pragma unroll 4
        for (int kk = 0; kk < 32; kk++) {
            int k = kc*32 + kk;
            float tv0 = t_s[p0][k],   tv1 = t_s[p0+1][k];
            float tv2 = t_s[p0+2][k], tv3 = t_s[p0+3][k];
            #pragma unroll
            for (int i = 0; i < 6; i++) {
                float wv = w_s[kk][ob + i];
                acc[i][0] = fmaf(wv, tv0, acc[i][0]);
                acc[i][1] = fmaf(wv, tv1, acc[i][1]);
                acc[i][2] = fmaf(wv, tv2, acc[i][2]);
                acc[i][3] = fmaf(wv, tv3, acc[i][3]);
            }
        }
    }

    #pragma unroll
    for (int i = 0; i < 6; i++) {
        int o = ob + i;
        float bo = bp[o];
        *(float4*)&outp[((size_t)b*96 + o)*HW + hw0 + p0] =
            make_float4(acc[i][0] + bo, acc[i][1] + bo,
                        acc[i][2] + bo, acc[i][3] + bo);
    }
}

// ---------------- launch ----------------------------------------------------
extern "C" void kernel_launch(void* const* d_in, const int* in_sizes, int n_in,
                              void* d_out, int out_size)
{
    const float* x   = (const float*)d_in[0];
    const float* Wv  = (const float*)d_in[1];
    const float* bv  = (const float*)d_in[2];
    const float* Wqk = (const float*)d_in[3];
    const float* bqk = (const float*)d_in[4];
    const float* Wm1 = (const float*)d_in[5];
    const float* bm1 = (const float*)d_in[6];
    const float* Wm2 = (const float*)d_in[7];
    const float* bm2 = (const float*)d_in[8];
    const float* Wdw = (const float*)d_in[9];
    const float* bdw = (const float*)d_in[10];
    const float* Wp  = (const float*)d_in[11];
    const float* bp  = (const float*)d_in[12];
    float* outp = (float*)d_out;

    bias_kernel <<<16, 256>>>(Wm1, bm1, Wm2, bm2);
    qkv_kernel  <<<dim3(4096, 6), 128>>>(x, Wqk, bqk, Wv, bv);
    dw_kernel   <<<24576, 256>>>(Wdw, bdw);
    attn_kernel <<<dim3(4096, 3), 64>>>();
    final_kernel<<<4096, 256>>>(Wp, bp, outp);
}